// round 5
// baseline (speedup 1.0000x reference)
#include <cuda_runtime.h>
#include <cstdint>

// Codec_35785667510396 — fused autoregressive PixelPred + RMSE + dual histograms.
// R5 (= R4 resubmit after infra failure): weights stored DUPLICATED in smem
// ([w,w] pairs) so FFMA2 operands load directly via LDS.128 with zero dup-MOVs;
// packed leaky via mul.rn.f32x2 + FMNMX.

typedef unsigned long long u64;

#define TPB 256
#define NB 2
#define BLOCKS_PER_CTA (TPB * NB)        // 512
#define CHUNKS (65536 / BLOCKS_PER_CTA)  // 128
#define NBC 48

__device__ double g_sumsq;
__device__ unsigned int g_hist_x[NBC * 256];
__device__ unsigned int g_hist_d[NBC * 256];

__device__ __forceinline__ u64 pack2(float lo, float hi) {
    u64 r; asm("mov.b64 %0, {%1, %2};" : "=l"(r) : "f"(lo), "f"(hi)); return r;
}
__device__ __forceinline__ float2 unpack2(u64 v) {
    float2 f; asm("mov.b64 {%0, %1}, %2;" : "=f"(f.x), "=f"(f.y) : "l"(v)); return f;
}
__device__ __forceinline__ u64 ffma2(u64 a, u64 b, u64 c) {
    u64 d; asm("fma.rn.f32x2 %0, %1, %2, %3;" : "=l"(d) : "l"(a), "l"(b), "l"(c)); return d;
}
__device__ __forceinline__ u64 mul2(u64 a, u64 b) {
    u64 d; asm("mul.rn.f32x2 %0, %1, %2;" : "=l"(d) : "l"(a), "l"(b)); return d;
}

// leaky(x) = max(x, 0.01x): packed mul + 2 per-lane FMNMX
__device__ __forceinline__ u64 leaky2(u64 a, u64 c001) {
    u64 m = mul2(a, c001);
    float2 f = unpack2(a), g = unpack2(m);
    return pack2(fmaxf(f.x, g.x), fmaxf(f.y, g.y));
}

__device__ __forceinline__ int binof(float v) {
    int t = (int)floorf((v + 1.0f) * 128.0f);
    t = max(t, 0); t = min(t, 255);
    return t;
}

// delta = x - clip(pred,-1,1); torch fmod(delta+1,2)-1 with t in [-1,3]
__device__ __forceinline__ float wrapdelta(float xv, float pred) {
    float p = fminf(fmaxf(pred, -1.0f), 1.0f);
    float t = (xv - p) + 1.0f;
    t = (t >= 2.0f) ? (t - 2.0f) : t;
    return t - 1.0f;
}

// ---- dynamic smem layout (all weights duplicated: each scalar stored twice) ----
#define OFF_W0D 0
#define OFF_B0D (OFF_W0D + 6144)
#define OFF_W1D (OFF_B0D + 384)
#define OFF_B1D (OFF_W1D + 4608)
#define OFF_W2D (OFF_B1D + 384)
#define OFF_B2D (OFF_W2D + 4608)
#define OFF_W3D (OFF_B2D + 384)
#define OFF_B3D (OFF_W3D + 384)
#define OFF_HX  (OFF_B3D + 32)
#define OFF_HD  (OFF_HX + 256)
#define OFF_WS  (OFF_HD + 256)
#define SMEM_FLOATS (OFF_WS + 8)
#define SMEM_BYTES (SMEM_FLOATS * 4)

__global__ void __launch_bounds__(TPB, 2) codec_main(
    const float* __restrict__ x,
    const float* __restrict__ W0, const float* __restrict__ b0,
    const float* __restrict__ W1, const float* __restrict__ b1,
    const float* __restrict__ W2, const float* __restrict__ b2,
    const float* __restrict__ W3, const float* __restrict__ b3)
{
    extern __shared__ __align__(16) float sm[];
    unsigned int* hx = (unsigned int*)(sm + OFF_HX);
    unsigned int* hd = (unsigned int*)(sm + OFF_HD);
    float* warpsums = sm + OFF_WS;

    const int tid = threadIdx.x;
    const int bc = blockIdx.x / CHUNKS;     // 0..47  (= b*3 + c)
    const int chunk = blockIdx.x % CHUNKS;
    const int c = bc % 3;

    // ---- load weights into smem, duplicated (W0 with inserted zero row) ----
    for (int idx = tid; idx < 16 * 16 * 12; idx += TPB) {
        int k = idx / 192; int r = idx % 192; int j = r / 12; int o = r % 12;
        float w = 0.0f;
        if (j != k) {
            int i = j - (j > k);
            w = W0[((c * 16 + k) * 15 + i) * 12 + o];
        }
        sm[OFF_W0D + idx * 2 + 0] = w;
        sm[OFF_W0D + idx * 2 + 1] = w;
    }
    for (int idx = tid; idx < 192; idx += TPB) {
        float v0 = b0[c * 192 + idx]; sm[OFF_B0D + idx * 2] = v0; sm[OFF_B0D + idx * 2 + 1] = v0;
        float v1 = b1[c * 192 + idx]; sm[OFF_B1D + idx * 2] = v1; sm[OFF_B1D + idx * 2 + 1] = v1;
        float v2 = b2[c * 192 + idx]; sm[OFF_B2D + idx * 2] = v2; sm[OFF_B2D + idx * 2 + 1] = v2;
        float v3 = W3[c * 192 + idx]; sm[OFF_W3D + idx * 2] = v3; sm[OFF_W3D + idx * 2 + 1] = v3;
    }
    for (int idx = tid; idx < 2304; idx += TPB) {
        float v1 = W1[c * 2304 + idx]; sm[OFF_W1D + idx * 2] = v1; sm[OFF_W1D + idx * 2 + 1] = v1;
        float v2 = W2[c * 2304 + idx]; sm[OFF_W2D + idx * 2] = v2; sm[OFF_W2D + idx * 2 + 1] = v2;
    }
    if (tid < 16) {
        float v3 = b3[c * 16 + tid];
        sm[OFF_B3D + tid * 2] = v3; sm[OFF_B3D + tid * 2 + 1] = v3;
    }
    hx[tid] = 0;
    hd[tid] = 0;
    __syncthreads();

    // ---- load 2 blocks of 16 pixels, packed into f32x2 lanes ----
    const int n0 = chunk * BLOCKS_PER_CTA + tid;   // block A
    const int n1 = n0 + TPB;                       // block B
    const float* xb = x + (size_t)bc * (1024 * 1024);
    const float* pA = xb + ((n0 >> 8) * 4096) + ((n0 & 255) * 4);
    const float* pB = xb + ((n1 >> 8) * 4096) + ((n1 & 255) * 4);

    u64 v[16];
#pragma unroll
    for (int r = 0; r < 4; r++) {
        float4 a  = *(const float4*)(pA + r * 1024);
        float4 bb = *(const float4*)(pB + r * 1024);
        v[r * 4 + 0] = pack2(a.x, bb.x);
        v[r * 4 + 1] = pack2(a.y, bb.y);
        v[r * 4 + 2] = pack2(a.z, bb.z);
        v[r * 4 + 3] = pack2(a.w, bb.w);
    }

    // ---- histogram of raw x ----
#pragma unroll
    for (int j = 0; j < 16; j++) {
        float2 f = unpack2(v[j]);
        atomicAdd(&hx[binof(f.x)], 1u);
        atomicAdd(&hx[binof(f.y)], 1u);
    }

    const u64 c001 = pack2(0.01f, 0.01f);

    // ---- autoregressive 16-step MLP chain ----
    float sq = 0.0f;
#pragma unroll 1
    for (int k = 0; k < 16; k++) {
        const u64* W0k = (const u64*)(sm + OFF_W0D) + k * 192;  // 16 rows x 12 dup-pairs
        const u64* b0k = (const u64*)(sm + OFF_B0D) + k * 12;
        const u64* W1k = (const u64*)(sm + OFF_W1D) + k * 144;
        const u64* b1k = (const u64*)(sm + OFF_B1D) + k * 12;
        const u64* W2k = (const u64*)(sm + OFF_W2D) + k * 144;
        const u64* b2k = (const u64*)(sm + OFF_B2D) + k * 12;
        const u64* W3k = (const u64*)(sm + OFF_W3D) + k * 12;
        const u64* b3k = (const u64*)(sm + OFF_B3D) + k;

        u64 acc[12];
        u64 h[12];

        // layer 0: 16 (padded) x 12
#pragma unroll
        for (int o = 0; o < 12; o++) acc[o] = b0k[o];
#pragma unroll
        for (int j = 0; j < 16; j++) {
            u64 vj = v[j];
            const ulonglong2* wp = (const ulonglong2*)(W0k + j * 12);
#pragma unroll
            for (int q = 0; q < 6; q++) {
                ulonglong2 w = wp[q];
                acc[q * 2 + 0] = ffma2(w.x, vj, acc[q * 2 + 0]);
                acc[q * 2 + 1] = ffma2(w.y, vj, acc[q * 2 + 1]);
            }
        }
#pragma unroll
        for (int o = 0; o < 12; o++) h[o] = leaky2(acc[o], c001);

        // layer 1: 12 x 12
#pragma unroll
        for (int o = 0; o < 12; o++) acc[o] = b1k[o];
#pragma unroll
        for (int i = 0; i < 12; i++) {
            u64 hi_ = h[i];
            const ulonglong2* wp = (const ulonglong2*)(W1k + i * 12);
#pragma unroll
            for (int q = 0; q < 6; q++) {
                ulonglong2 w = wp[q];
                acc[q * 2 + 0] = ffma2(w.x, hi_, acc[q * 2 + 0]);
                acc[q * 2 + 1] = ffma2(w.y, hi_, acc[q * 2 + 1]);
            }
        }
#pragma unroll
        for (int o = 0; o < 12; o++) h[o] = leaky2(acc[o], c001);

        // layer 2: 12 x 12
#pragma unroll
        for (int o = 0; o < 12; o++) acc[o] = b2k[o];
#pragma unroll
        for (int i = 0; i < 12; i++) {
            u64 hi_ = h[i];
            const ulonglong2* wp = (const ulonglong2*)(W2k + i * 12);
#pragma unroll
            for (int q = 0; q < 6; q++) {
                ulonglong2 w = wp[q];
                acc[q * 2 + 0] = ffma2(w.x, hi_, acc[q * 2 + 0]);
                acc[q * 2 + 1] = ffma2(w.y, hi_, acc[q * 2 + 1]);
            }
        }
#pragma unroll
        for (int o = 0; o < 12; o++) h[o] = leaky2(acc[o], c001);

        // layer 3: 12 -> 1
        u64 acc3 = b3k[0];
        {
            const ulonglong2* wp = (const ulonglong2*)W3k;
#pragma unroll
            for (int q = 0; q < 6; q++) {
                ulonglong2 w = wp[q];
                acc3 = ffma2(w.x, h[q * 2 + 0], acc3);
                acc3 = ffma2(w.y, h[q * 2 + 1], acc3);
            }
        }

        // read x_k (predicated select, no dynamic index)
        u64 xk = v[0];
#pragma unroll
        for (int j = 1; j < 16; j++) if (j == k) xk = v[j];

        float2 p  = unpack2(acc3);
        float2 xv = unpack2(xk);
        float e0 = wrapdelta(xv.x, p.x);
        float e1 = wrapdelta(xv.y, p.y);
        sq += e0 * e0 + e1 * e1;
        atomicAdd(&hd[binof(e0)], 1u);
        atomicAdd(&hd[binof(e1)], 1u);

        u64 ev = pack2(e0, e1);
#pragma unroll
        for (int j = 0; j < 16; j++) if (j == k) v[j] = ev;
    }

    // ---- reductions ----
#pragma unroll
    for (int off = 16; off; off >>= 1) sq += __shfl_xor_sync(0xFFFFFFFFu, sq, off);
    if ((tid & 31) == 0) warpsums[tid >> 5] = sq;
    __syncthreads();
    if (tid == 0) {
        float t = 0.0f;
#pragma unroll
        for (int w = 0; w < 8; w++) t += warpsums[w];
        atomicAdd(&g_sumsq, (double)t);
    }
    atomicAdd(&g_hist_x[bc * 256 + tid], hx[tid]);
    atomicAdd(&g_hist_d[bc * 256 + tid], hd[tid]);
}

__global__ void codec_zero() {
    int t = blockIdx.x * blockDim.x + threadIdx.x;
    if (t < NBC * 256) { g_hist_x[t] = 0; g_hist_d[t] = 0; }
    if (t == 0) g_sumsq = 0.0;
}

__global__ void codec_final(float* __restrict__ out) {
    __shared__ double red[256];
    const int t = threadIdx.x;
    const float invres = 1.0f / 1048576.0f;
    double ex = 0.0, ed = 0.0;
    for (int i = t; i < NBC * 256; i += 256) {
        float px = (float)g_hist_x[i] * invres;
        if (px > 0.0f) ex += (double)(-px * log2f(px));
        float pd = (float)g_hist_d[i] * invres;
        if (pd > 0.0f) ed += (double)(-pd * log2f(pd));
    }
    red[t] = ex;
    __syncthreads();
    for (int sft = 128; sft; sft >>= 1) {
        if (t < sft) red[t] += red[t + sft];
        __syncthreads();
    }
    double entx = red[0];
    __syncthreads();
    red[t] = ed;
    __syncthreads();
    for (int sft = 128; sft; sft >>= 1) {
        if (t < sft) red[t] += red[t + sft];
        __syncthreads();
    }
    double entd = red[0];
    if (t == 0) {
        double mean = g_sumsq / 50331648.0;   // 16*3*65536*16
        out[0] = 255.0f * (float)sqrt(mean);
        out[1] = (float)(entx / 384.0);       // 8 * nch, nch=48
        out[2] = (float)(entd / 384.0);
    }
}

extern "C" void kernel_launch(void* const* d_in, const int* in_sizes, int n_in,
                              void* d_out, int out_size) {
    const float* x  = (const float*)d_in[0];
    const float* W0 = (const float*)d_in[1];
    const float* b0 = (const float*)d_in[2];
    const float* W1 = (const float*)d_in[3];
    const float* b1 = (const float*)d_in[4];
    const float* W2 = (const float*)d_in[5];
    const float* b2 = (const float*)d_in[6];
    const float* W3 = (const float*)d_in[7];
    const float* b3 = (const float*)d_in[8];

    static int smem_set = 0;
    if (!smem_set) {
        cudaFuncSetAttribute(codec_main, cudaFuncAttributeMaxDynamicSharedMemorySize, SMEM_BYTES);
        smem_set = 1;
    }

    codec_zero<<<NBC, 256>>>();
    codec_main<<<NBC * CHUNKS, TPB, SMEM_BYTES>>>(x, W0, b0, W1, b1, W2, b2, W3, b3);
    codec_final<<<1, 256>>>((float*)d_out);
}

// round 8
// speedup vs baseline: 1.2067x; 1.2067x over previous
#include <cuda_runtime.h>
#include <cstdint>

// Codec_35785667510396 — fused autoregressive PixelPred + RMSE + dual histograms.
// R8: OUTPUT-pair packing for FFMA2 (weight pairs (o,o+1) are contiguous in the
// original layout -> LDS.128 yields 2 ready packed operands, zero duplication).
// Only inputs get dup'd (1 MOV reused across 6 output-pairs). NB=2 blocks/thread,
// TPB=256 (same shape as the known-running R3/R5 binaries).

typedef unsigned long long u64;

#define TPB 256
#define NB 2
#define BLOCKS_PER_CTA (TPB * NB)        // 512
#define CHUNKS (65536 / BLOCKS_PER_CTA)  // 128
#define NBC 48

__device__ double g_sumsq;
__device__ unsigned int g_hist_x[NBC * 256];
__device__ unsigned int g_hist_d[NBC * 256];

__device__ __forceinline__ u64 pack2(float lo, float hi) {
    u64 r; asm("mov.b64 %0, {%1, %2};" : "=l"(r) : "f"(lo), "f"(hi)); return r;
}
__device__ __forceinline__ float2 unpack2(u64 v) {
    float2 f; asm("mov.b64 {%0, %1}, %2;" : "=f"(f.x), "=f"(f.y) : "l"(v)); return f;
}
__device__ __forceinline__ u64 ffma2(u64 a, u64 b, u64 c) {
    u64 d; asm("fma.rn.f32x2 %0, %1, %2, %3;" : "=l"(d) : "l"(a), "l"(b), "l"(c)); return d;
}
__device__ __forceinline__ u64 mul2(u64 a, u64 b) {
    u64 d; asm("mul.rn.f32x2 %0, %1, %2;" : "=l"(d) : "l"(a), "l"(b)); return d;
}
__device__ __forceinline__ u64 dupf(float s) { return pack2(s, s); }

// leaky(x) = max(x, 0.01x) applied to a packed pair
__device__ __forceinline__ float2 leaky2f(u64 a, u64 c001) {
    u64 m = mul2(a, c001);
    float2 f = unpack2(a), g = unpack2(m);
    f.x = fmaxf(f.x, g.x);
    f.y = fmaxf(f.y, g.y);
    return f;
}

__device__ __forceinline__ int binof(float v) {
    int t = (int)floorf((v + 1.0f) * 128.0f);
    t = max(t, 0); t = min(t, 255);
    return t;
}

// delta = x - clip(pred,-1,1); torch fmod(delta+1,2)-1 with t in [-1,3]
__device__ __forceinline__ float wrapdelta(float xv, float pred) {
    float p = fminf(fmaxf(pred, -1.0f), 1.0f);
    float t = (xv - p) + 1.0f;
    t = (t >= 2.0f) ? (t - 2.0f) : t;
    return t - 1.0f;
}

struct __align__(16) Smem {
    float W0p[16 * 16 * 12];  // padded: zero row at j==k; 12 outputs contiguous
    float b0[16 * 12];
    float W1[16 * 144];
    float b1[16 * 12];
    float W2[16 * 144];
    float b2[16 * 12];
    float W3[16 * 12];
    float b3[16];
    unsigned int hx[256];
    unsigned int hd[256];
    float warpsums[8];
};

__global__ void __launch_bounds__(TPB, 2) codec_main(
    const float* __restrict__ x,
    const float* __restrict__ W0, const float* __restrict__ b0,
    const float* __restrict__ W1, const float* __restrict__ b1,
    const float* __restrict__ W2, const float* __restrict__ b2,
    const float* __restrict__ W3, const float* __restrict__ b3)
{
    __shared__ Smem s;
    const int tid = threadIdx.x;
    const int bc = blockIdx.x / CHUNKS;     // 0..47  (= b*3 + c)
    const int chunk = blockIdx.x % CHUNKS;
    const int c = bc % 3;

    // ---- load weights into smem (W0 with inserted zero row at j==k) ----
    for (int idx = tid; idx < 16 * 16 * 12; idx += TPB) {
        int k = idx / 192; int r = idx % 192; int j = r / 12; int o = r % 12;
        float w = 0.0f;
        if (j != k) {
            int i = j - (j > k);
            w = W0[((c * 16 + k) * 15 + i) * 12 + o];
        }
        s.W0p[idx] = w;
    }
    for (int idx = tid; idx < 192; idx += TPB) {
        s.b0[idx] = b0[c * 192 + idx];
        s.b1[idx] = b1[c * 192 + idx];
        s.b2[idx] = b2[c * 192 + idx];
        s.W3[idx] = W3[c * 192 + idx];
    }
    for (int idx = tid; idx < 2304; idx += TPB) {
        s.W1[idx] = W1[c * 2304 + idx];
        s.W2[idx] = W2[c * 2304 + idx];
    }
    if (tid < 16) s.b3[tid] = b3[c * 16 + tid];
    s.hx[tid] = 0;
    s.hd[tid] = 0;
    __syncthreads();

    // ---- load 2 blocks of 16 pixels each (scalar register arrays) ----
    float vs[NB][16];
#pragma unroll
    for (int b = 0; b < NB; b++) {
        const int n = chunk * BLOCKS_PER_CTA + b * TPB + tid;
        const float* p = x + (size_t)bc * (1024 * 1024) + ((n >> 8) * 4096) + ((n & 255) * 4);
#pragma unroll
        for (int r = 0; r < 4; r++) {
            float4 a = *(const float4*)(p + r * 1024);
            vs[b][r * 4 + 0] = a.x;
            vs[b][r * 4 + 1] = a.y;
            vs[b][r * 4 + 2] = a.z;
            vs[b][r * 4 + 3] = a.w;
        }
    }

    // ---- histogram of raw x ----
#pragma unroll
    for (int b = 0; b < NB; b++)
#pragma unroll
        for (int j = 0; j < 16; j++)
            atomicAdd(&s.hx[binof(vs[b][j])], 1u);

    const u64 c001 = pack2(0.01f, 0.01f);

    // ---- autoregressive 16-step MLP chain ----
    float sq = 0.0f;
#pragma unroll 1
    for (int k = 0; k < 16; k++) {
        const float* W0k = s.W0p + k * 192;
        const float* W1k = s.W1 + k * 144;
        const float* W2k = s.W2 + k * 144;

        u64 acc[NB][6];     // 6 output-pairs per block
        float hs[NB][12];   // hidden scalars

        // ---- layer 0: 16 (padded) inputs x 12 outputs ----
        {
            const ulonglong2* bp = (const ulonglong2*)(s.b0 + k * 12);
            ulonglong2 t0 = bp[0], t1 = bp[1], t2 = bp[2];
#pragma unroll
            for (int b = 0; b < NB; b++) {
                acc[b][0] = t0.x; acc[b][1] = t0.y;
                acc[b][2] = t1.x; acc[b][3] = t1.y;
                acc[b][4] = t2.x; acc[b][5] = t2.y;
            }
        }
#pragma unroll
        for (int j = 0; j < 16; j++) {
            const ulonglong2* wp = (const ulonglong2*)(W0k + j * 12);
            ulonglong2 w0 = wp[0], w1 = wp[1], w2 = wp[2];
#pragma unroll
            for (int b = 0; b < NB; b++) {
                u64 vd = dupf(vs[b][j]);
                acc[b][0] = ffma2(w0.x, vd, acc[b][0]);
                acc[b][1] = ffma2(w0.y, vd, acc[b][1]);
                acc[b][2] = ffma2(w1.x, vd, acc[b][2]);
                acc[b][3] = ffma2(w1.y, vd, acc[b][3]);
                acc[b][4] = ffma2(w2.x, vd, acc[b][4]);
                acc[b][5] = ffma2(w2.y, vd, acc[b][5]);
            }
        }
#pragma unroll
        for (int b = 0; b < NB; b++)
#pragma unroll
            for (int q = 0; q < 6; q++) {
                float2 f = leaky2f(acc[b][q], c001);
                hs[b][2 * q] = f.x; hs[b][2 * q + 1] = f.y;
            }

        // ---- layer 1: 12 x 12 ----
        {
            const ulonglong2* bp = (const ulonglong2*)(s.b1 + k * 12);
            ulonglong2 t0 = bp[0], t1 = bp[1], t2 = bp[2];
#pragma unroll
            for (int b = 0; b < NB; b++) {
                acc[b][0] = t0.x; acc[b][1] = t0.y;
                acc[b][2] = t1.x; acc[b][3] = t1.y;
                acc[b][4] = t2.x; acc[b][5] = t2.y;
            }
        }
#pragma unroll
        for (int i = 0; i < 12; i++) {
            const ulonglong2* wp = (const ulonglong2*)(W1k + i * 12);
            ulonglong2 w0 = wp[0], w1 = wp[1], w2 = wp[2];
#pragma unroll
            for (int b = 0; b < NB; b++) {
                u64 hd2 = dupf(hs[b][i]);
                acc[b][0] = ffma2(w0.x, hd2, acc[b][0]);
                acc[b][1] = ffma2(w0.y, hd2, acc[b][1]);
                acc[b][2] = ffma2(w1.x, hd2, acc[b][2]);
                acc[b][3] = ffma2(w1.y, hd2, acc[b][3]);
                acc[b][4] = ffma2(w2.x, hd2, acc[b][4]);
                acc[b][5] = ffma2(w2.y, hd2, acc[b][5]);
            }
        }
#pragma unroll
        for (int b = 0; b < NB; b++)
#pragma unroll
            for (int q = 0; q < 6; q++) {
                float2 f = leaky2f(acc[b][q], c001);
                hs[b][2 * q] = f.x; hs[b][2 * q + 1] = f.y;
            }

        // ---- layer 2: 12 x 12 ----
        {
            const ulonglong2* bp = (const ulonglong2*)(s.b2 + k * 12);
            ulonglong2 t0 = bp[0], t1 = bp[1], t2 = bp[2];
#pragma unroll
            for (int b = 0; b < NB; b++) {
                acc[b][0] = t0.x; acc[b][1] = t0.y;
                acc[b][2] = t1.x; acc[b][3] = t1.y;
                acc[b][4] = t2.x; acc[b][5] = t2.y;
            }
        }
#pragma unroll
        for (int i = 0; i < 12; i++) {
            const ulonglong2* wp = (const ulonglong2*)(W2k + i * 12);
            ulonglong2 w0 = wp[0], w1 = wp[1], w2 = wp[2];
#pragma unroll
            for (int b = 0; b < NB; b++) {
                u64 hd2 = dupf(hs[b][i]);
                acc[b][0] = ffma2(w0.x, hd2, acc[b][0]);
                acc[b][1] = ffma2(w0.y, hd2, acc[b][1]);
                acc[b][2] = ffma2(w1.x, hd2, acc[b][2]);
                acc[b][3] = ffma2(w1.y, hd2, acc[b][3]);
                acc[b][4] = ffma2(w2.x, hd2, acc[b][4]);
                acc[b][5] = ffma2(w2.y, hd2, acc[b][5]);
            }
        }

        // ---- layer 3: 12 -> 1 (packed dot + horizontal add) ----
        {
            const ulonglong2* wp = (const ulonglong2*)(s.W3 + k * 12);
            ulonglong2 w0 = wp[0], w1 = wp[1], w2 = wp[2];
            const float b3s = s.b3[k];
#pragma unroll
            for (int b = 0; b < NB; b++) {
                u64 a3 = 0;  // pack2(0,0)
#pragma unroll
                for (int q = 0; q < 6; q++) {
                    float2 f = leaky2f(acc[b][q], c001);
                    u64 hp = pack2(f.x, f.y);
                    u64 wq = (q < 2) ? ((q == 0) ? w0.x : w0.y)
                           : (q < 4) ? ((q == 2) ? w1.x : w1.y)
                                     : ((q == 4) ? w2.x : w2.y);
                    a3 = ffma2(wq, hp, a3);
                }
                float2 pf = unpack2(a3);
                float pred = pf.x + pf.y + b3s;

                // x_k select (compile-time chain over runtime k)
                float xk = vs[b][0];
#pragma unroll
                for (int j = 1; j < 16; j++) if (j == k) xk = vs[b][j];

                float e = wrapdelta(xk, pred);
                sq += e * e;
                atomicAdd(&s.hd[binof(e)], 1u);
#pragma unroll
                for (int j = 0; j < 16; j++) if (j == k) vs[b][j] = e;
            }
        }
    }

    // ---- reductions ----
#pragma unroll
    for (int off = 16; off; off >>= 1) sq += __shfl_xor_sync(0xFFFFFFFFu, sq, off);
    if ((tid & 31) == 0) s.warpsums[tid >> 5] = sq;
    __syncthreads();
    if (tid == 0) {
        float t = 0.0f;
#pragma unroll
        for (int w = 0; w < 8; w++) t += s.warpsums[w];
        atomicAdd(&g_sumsq, (double)t);
    }
    atomicAdd(&g_hist_x[bc * 256 + tid], s.hx[tid]);
    atomicAdd(&g_hist_d[bc * 256 + tid], s.hd[tid]);
}

__global__ void codec_zero() {
    int t = blockIdx.x * blockDim.x + threadIdx.x;
    if (t < NBC * 256) { g_hist_x[t] = 0; g_hist_d[t] = 0; }
    if (t == 0) g_sumsq = 0.0;
}

__global__ void codec_final(float* __restrict__ out) {
    __shared__ double red[256];
    const int t = threadIdx.x;
    const float invres = 1.0f / 1048576.0f;
    double ex = 0.0, ed = 0.0;
    for (int i = t; i < NBC * 256; i += 256) {
        float px = (float)g_hist_x[i] * invres;
        if (px > 0.0f) ex += (double)(-px * log2f(px));
        float pd = (float)g_hist_d[i] * invres;
        if (pd > 0.0f) ed += (double)(-pd * log2f(pd));
    }
    red[t] = ex;
    __syncthreads();
    for (int sft = 128; sft; sft >>= 1) {
        if (t < sft) red[t] += red[t + sft];
        __syncthreads();
    }
    double entx = red[0];
    __syncthreads();
    red[t] = ed;
    __syncthreads();
    for (int sft = 128; sft; sft >>= 1) {
        if (t < sft) red[t] += red[t + sft];
        __syncthreads();
    }
    double entd = red[0];
    if (t == 0) {
        double mean = g_sumsq / 50331648.0;   // 16*3*65536*16
        out[0] = 255.0f * (float)sqrt(mean);
        out[1] = (float)(entx / 384.0);       // 8 * nch, nch=48
        out[2] = (float)(entd / 384.0);
    }
}

extern "C" void kernel_launch(void* const* d_in, const int* in_sizes, int n_in,
                              void* d_out, int out_size) {
    const float* x  = (const float*)d_in[0];
    const float* W0 = (const float*)d_in[1];
    const float* b0 = (const float*)d_in[2];
    const float* W1 = (const float*)d_in[3];
    const float* b1 = (const float*)d_in[4];
    const float* W2 = (const float*)d_in[5];
    const float* b2 = (const float*)d_in[6];
    const float* W3 = (const float*)d_in[7];
    const float* b3 = (const float*)d_in[8];

    codec_zero<<<NBC, 256>>>();
    codec_main<<<NBC * CHUNKS, TPB>>>(x, W0, b0, W1, b1, W2, b2, W3, b3);
    codec_final<<<1, 256>>>((float*)d_out);
}